// round 4
// baseline (speedup 1.0000x reference)
#include <cuda_runtime.h>
#include <cuda_bf16.h>

#define TT   65536
#define BB   4
#define W    16
#define NL   18
#define TILE4 512      // timesteps per CTA
#define NTH  128       // threads per CTA; 4 ts per thread
#define HOFF 1856      // float offset of h tile in dynamic smem

typedef unsigned long long u64;

__device__ float g_h0[(size_t)BB * TT * W];
__device__ float g_h1[(size_t)BB * TT * W];

__device__ __forceinline__ u64 pk2(float x){ u64 r; asm("mov.b64 %0,{%1,%1};":"=l"(r):"f"(x)); return r; }
__device__ __forceinline__ u64 pk(float lo, float hi){ u64 r; asm("mov.b64 %0,{%1,%2};":"=l"(r):"f"(lo),"f"(hi)); return r; }
__device__ __forceinline__ void unpk(u64 v, float& lo, float& hi){ asm("mov.b64 {%0,%1},%2;":"=f"(lo),"=f"(hi):"l"(v)); }
__device__ __forceinline__ u64 fma2(u64 a, u64 b, u64 c){ u64 d; asm("fma.rn.f32x2 %0,%1,%2,%3;":"=l"(d):"l"(a),"l"(b),"l"(c)); return d; }
__device__ __forceinline__ u64 mul2(u64 a, u64 b){ u64 d; asm("mul.rn.f32x2 %0,%1,%2;":"=l"(d):"l"(a),"l"(b)); return d; }
__device__ __forceinline__ u64 add2(u64 a, u64 b){ u64 d; asm("add.rn.f32x2 %0,%1,%2;":"=l"(d):"l"(a),"l"(b)); return d; }
__device__ __forceinline__ float rcpf(float x){ float r; asm("rcp.approx.f32 %0,%1;":"=f"(r):"f"(x)); return r; }

#define ABS2 0x7FFFFFFF7FFFFFFFull
#define ONE2 0x3F8000003F800000ull

// z = softsign(f)*softsign(g) = f*g / ((1+|f|)(1+|g|)), packed over 2 channels
__device__ __forceinline__ u64 ssz(u64 f, u64 g){
    u64 df = add2(f & ABS2, ONE2);
    u64 dg = add2(g & ABS2, ONE2);
    u64 dd = mul2(df, dg);
    float dl, dh; unpk(dd, dl, dh);
    u64 rr = pk(rcpf(dl), rcpf(dh));
    return mul2(mul2(f, g), rr);
}

__global__ void start_kernel(const float* __restrict__ x,
                             const float* __restrict__ sw,
                             float* __restrict__ out) {
    int idx = blockIdx.x * blockDim.x + threadIdx.x;  // over B*T
    if (idx < BB * TT) {
        float xv = x[idx];
        #pragma unroll
        for (int o = 0; o < W; o++) g_h0[(size_t)idx * W + o] = sw[o] * xv;
        out[idx] = 0.f;
    }
}

// Row stride padded so the transpose-store STS pattern is conflict-free:
// want R % 8 == 2  =>  4R % 32 == 8  => channel banks {0,8,16,24}.
__host__ __device__ __forceinline__ int padR(int d) {
    int R = TILE4 + 2 * d;
    R += ((2 - (R & 7)) + 8) & 7;
    return R;
}

// Dynamic smem layout (floats):
//  [0    :1536)  conv+gate weights, ((k*16+i)*32 + half*16 + o); half0=f, half1=g
//  [1536 :1792)  res weights transposed rsm[i][o]
//  [1792 :1808)  mixer msm[o]
//  [1808 :1824)  conv bias, [1824:1840) gate bias, [1840:1856) res bias
//  [1856 :    )  h tile, channel-major: hT[ch][R]
__global__ __launch_bounds__(NTH, 3)
void layer4_kernel(const float* __restrict__ cw, const float* __restrict__ cb,
                   const float* __restrict__ gw, const float* __restrict__ gb,
                   const float* __restrict__ rw, const float* __restrict__ rb,
                   const float* __restrict__ mix, float* __restrict__ out,
                   int li, int d, int last)
{
    extern __shared__ float sh[];
    const float* hin  = (li & 1) ? g_h1 : g_h0;
    float*       hout = (li & 1) ? g_h0 : g_h1;
    const int b   = blockIdx.y;
    const int t0  = blockIdx.x * TILE4;
    const int tid = threadIdx.x;
    const int R   = padR(d);
    float* hT = sh + HOFF;

    // ---- weight prep (once per block) ----
    for (int w = tid; w < 1536; w += NTH) {
        int k = w >> 9, rem = w & 511;
        int i = rem >> 5, half = (rem >> 4) & 1, o = rem & 15;
        const float* src = half ? gw : cw;
        sh[w] = src[li * 768 + o * 48 + i * 3 + k];
    }
    for (int w = tid; w < 256; w += NTH) {
        int i = w >> 4, o = w & 15;
        sh[1536 + w] = last ? 0.f : rw[li * 256 + o * 16 + i];
    }
    if (tid < 16) {
        sh[1792 + tid] = mix[li * 16 + tid];
        sh[1808 + tid] = cb[li * 16 + tid];
        sh[1824 + tid] = gb[li * 16 + tid];
        sh[1840 + tid] = last ? 0.f : rb[li * 16 + tid];
    }

    // ---- h tile load, transposing [t][ch] -> [ch][t] ----
    {
        const int nrows = TILE4 + 2 * d;
        const int n4 = nrows * 4;  // float4 chunks
        for (int idx = tid; idx < n4; idx += NTH) {
            int r = idx >> 2, c = idx & 3;
            int gt = t0 - 2 * d + r;
            float4 v = make_float4(0.f, 0.f, 0.f, 0.f);
            if (gt >= 0)
                v = *(const float4*)(hin + ((size_t)b * TT + gt) * W + 4 * c);
            hT[(4 * c + 0) * R + r] = v.x;
            hT[(4 * c + 1) * R + r] = v.y;
            hT[(4 * c + 2) * R + r] = v.z;
            hT[(4 * c + 3) * R + r] = v.w;
        }
    }
    __syncthreads();

    // ---- compute: this thread owns timesteps t0 + 4*tid + {0,1,2,3} ----
    u64 f0[8], f1[8], f2[8], f3[8], g0[8], g1[8], g2[8], g3[8];
    {
        const u64* bp = (const u64*)(sh + 1808);
        #pragma unroll
        for (int p = 0; p < 8; p++) {
            u64 cbv = bp[p], gbv = bp[8 + p];
            f0[p] = cbv; f1[p] = cbv; f2[p] = cbv; f3[p] = cbv;
            g0[p] = gbv; g1[p] = gbv; g2[p] = gbv; g3[p] = gbv;
        }
    }

    #pragma unroll 1
    for (int k = 0; k < 3; k++) {
        const float* tp = hT + k * d + 4 * tid;   // tap column for this k
        #pragma unroll
        for (int i = 0; i < 16; i++) {
            const float* row = tp + i * R;
            u64 hp0 = pk2(row[0]);
            u64 hp1 = pk2(row[1]);
            u64 hp2 = pk2(row[2]);
            u64 hp3 = pk2(row[3]);
            const ulonglong2* wp = (const ulonglong2*)(sh) + (k * 16 + i) * 8;
            #pragma unroll
            for (int q = 0; q < 4; q++) {
                ulonglong2 wf = wp[q];
                ulonglong2 wg = wp[4 + q];
                f0[2*q]   = fma2(wf.x, hp0, f0[2*q]);
                f0[2*q+1] = fma2(wf.y, hp0, f0[2*q+1]);
                f1[2*q]   = fma2(wf.x, hp1, f1[2*q]);
                f1[2*q+1] = fma2(wf.y, hp1, f1[2*q+1]);
                f2[2*q]   = fma2(wf.x, hp2, f2[2*q]);
                f2[2*q+1] = fma2(wf.y, hp2, f2[2*q+1]);
                f3[2*q]   = fma2(wf.x, hp3, f3[2*q]);
                f3[2*q+1] = fma2(wf.y, hp3, f3[2*q+1]);
                g0[2*q]   = fma2(wg.x, hp0, g0[2*q]);
                g0[2*q+1] = fma2(wg.y, hp0, g0[2*q+1]);
                g1[2*q]   = fma2(wg.x, hp1, g1[2*q]);
                g1[2*q+1] = fma2(wg.y, hp1, g1[2*q+1]);
                g2[2*q]   = fma2(wg.x, hp2, g2[2*q]);
                g2[2*q+1] = fma2(wg.y, hp2, g2[2*q+1]);
                g3[2*q]   = fma2(wg.x, hp3, g3[2*q]);
                g3[2*q+1] = fma2(wg.y, hp3, g3[2*q+1]);
            }
        }
    }

    // ---- gated activation (z overwrites f) ----
    #pragma unroll
    for (int p = 0; p < 8; p++) {
        f0[p] = ssz(f0[p], g0[p]);
        f1[p] = ssz(f1[p], g1[p]);
        f2[p] = ssz(f2[p], g2[p]);
        f3[p] = ssz(f3[p], g3[p]);
    }

    // ---- mixer: m_ts = sum_o mix[o]*z_ts[o]; out float4 RMW ----
    {
        const u64* mp = (const u64*)(sh + 1792);
        u64 m0 = mul2(mp[0], f0[0]);
        u64 m1 = mul2(mp[0], f1[0]);
        u64 m2 = mul2(mp[0], f2[0]);
        u64 m3 = mul2(mp[0], f3[0]);
        #pragma unroll
        for (int p = 1; p < 8; p++) {
            m0 = fma2(mp[p], f0[p], m0);
            m1 = fma2(mp[p], f1[p], m1);
            m2 = fma2(mp[p], f2[p], m2);
            m3 = fma2(mp[p], f3[p], m3);
        }
        float a, c;
        float4* op = (float4*)(out + (size_t)b * TT + t0 + 4 * tid);
        float4 ov = *op;
        unpk(m0, a, c); ov.x += a + c;
        unpk(m1, a, c); ov.y += a + c;
        unpk(m2, a, c); ov.z += a + c;
        unpk(m3, a, c); ov.w += a + c;
        *op = ov;
    }

    // ---- residual + write next h (two ts at a time to cap live regs) ----
    if (!last) {
        const u64* rbp = (const u64*)(sh + 1840);
        const size_t base = ((size_t)b * TT + t0 + 4 * tid) * W;

        #pragma unroll
        for (int half = 0; half < 2; half++) {
            u64* zA = half ? f2 : f0;
            u64* zB = half ? f3 : f1;
            float zfA[16], zfB[16];
            #pragma unroll
            for (int p = 0; p < 8; p++) {
                unpk(zA[p], zfA[2*p], zfA[2*p+1]);
                unpk(zB[p], zfB[2*p], zfB[2*p+1]);
            }
            u64 hnA[8], hnB[8];
            {
                const ulonglong2* sA = (const ulonglong2*)(hin + base + (2*half)     * W);
                const ulonglong2* sB = (const ulonglong2*)(hin + base + (2*half + 1) * W);
                #pragma unroll
                for (int q = 0; q < 4; q++) {
                    ulonglong2 a = sA[q];
                    ulonglong2 c = sB[q];
                    hnA[2*q]   = add2(a.x, rbp[2*q]);
                    hnA[2*q+1] = add2(a.y, rbp[2*q+1]);
                    hnB[2*q]   = add2(c.x, rbp[2*q]);
                    hnB[2*q+1] = add2(c.y, rbp[2*q+1]);
                }
            }
            #pragma unroll
            for (int i = 0; i < 16; i++) {
                u64 zpA = pk2(zfA[i]);
                u64 zpB = pk2(zfB[i]);
                const ulonglong2* rp = (const ulonglong2*)(sh + 1536) + i * 4;
                #pragma unroll
                for (int q = 0; q < 4; q++) {
                    ulonglong2 rr = rp[q];
                    hnA[2*q]   = fma2(rr.x, zpA, hnA[2*q]);
                    hnA[2*q+1] = fma2(rr.y, zpA, hnA[2*q+1]);
                    hnB[2*q]   = fma2(rr.x, zpB, hnB[2*q]);
                    hnB[2*q+1] = fma2(rr.y, zpB, hnB[2*q+1]);
                }
            }
            {
                ulonglong2* oA = (ulonglong2*)(hout + base + (2*half)     * W);
                ulonglong2* oB = (ulonglong2*)(hout + base + (2*half + 1) * W);
                #pragma unroll
                for (int q = 0; q < 4; q++) {
                    oA[q] = make_ulonglong2(hnA[2*q], hnA[2*q+1]);
                    oB[q] = make_ulonglong2(hnB[2*q], hnB[2*q+1]);
                }
            }
        }
    }
}

extern "C" void kernel_launch(void* const* d_in, const int* in_sizes, int n_in,
                              void* d_out, int out_size) {
    const float* x   = (const float*)d_in[0];
    const float* sw  = (const float*)d_in[1];
    const float* cw  = (const float*)d_in[2];
    const float* cb  = (const float*)d_in[3];
    const float* gw  = (const float*)d_in[4];
    const float* gb  = (const float*)d_in[5];
    const float* rw  = (const float*)d_in[6];
    const float* rb  = (const float*)d_in[7];
    const float* mix = (const float*)d_in[8];
    float* out = (float*)d_out;

    static const int dil[NL] = {1,2,4,8,16,32,64,128,256,
                                1,2,4,8,16,32,64,128,256};

    const int max_smem = (HOFF + W * padR(256)) * (int)sizeof(float);
    cudaFuncSetAttribute(layer4_kernel,
                         cudaFuncAttributeMaxDynamicSharedMemorySize, max_smem);

    start_kernel<<<(BB * TT + 255) / 256, 256>>>(x, sw, out);

    dim3 grid(TT / TILE4, BB);
    for (int li = 0; li < NL; li++) {
        int d = dil[li];
        int smem = (HOFF + W * padR(d)) * (int)sizeof(float);
        layer4_kernel<<<grid, NTH, smem>>>(
            cw, cb, gw, gb, rw, rb, mix, out,
            li, d, (li == NL - 1) ? 1 : 0);
    }
}

// round 5
// speedup vs baseline: 1.3093x; 1.3093x over previous
#include <cuda_runtime.h>
#include <cuda_bf16.h>

#define TT   65536
#define BB   4
#define W    16
#define NL   18
#define TILE 512       // timesteps per CTA
#define NTH  128       // threads; thread owns ts tid + 128*m, m=0..3
#define HOFF 1856      // float offset of h tile in dynamic smem

typedef unsigned long long u64;

__device__ float g_h0[(size_t)BB * TT * W];
__device__ float g_h1[(size_t)BB * TT * W];

__device__ __forceinline__ u64 pk2(float x){ u64 r; asm("mov.b64 %0,{%1,%1};":"=l"(r):"f"(x)); return r; }
__device__ __forceinline__ u64 pk(float lo, float hi){ u64 r; asm("mov.b64 %0,{%1,%2};":"=l"(r):"f"(lo),"f"(hi)); return r; }
__device__ __forceinline__ void unpk(u64 v, float& lo, float& hi){ asm("mov.b64 {%0,%1},%2;":"=f"(lo),"=f"(hi):"l"(v)); }
__device__ __forceinline__ u64 fma2(u64 a, u64 b, u64 c){ u64 d; asm("fma.rn.f32x2 %0,%1,%2,%3;":"=l"(d):"l"(a),"l"(b),"l"(c)); return d; }
__device__ __forceinline__ u64 mul2(u64 a, u64 b){ u64 d; asm("mul.rn.f32x2 %0,%1,%2;":"=l"(d):"l"(a),"l"(b)); return d; }
__device__ __forceinline__ u64 add2(u64 a, u64 b){ u64 d; asm("add.rn.f32x2 %0,%1,%2;":"=l"(d):"l"(a),"l"(b)); return d; }
__device__ __forceinline__ float rcpf(float x){ float r; asm("rcp.approx.f32 %0,%1;":"=f"(r):"f"(x)); return r; }

#define ABS2 0x7FFFFFFF7FFFFFFFull
#define ONE2 0x3F8000003F800000ull

// z = softsign(f)*softsign(g) = f*g / ((1+|f|)(1+|g|)), packed over 2 channels
__device__ __forceinline__ u64 ssz(u64 f, u64 g){
    u64 df = add2(f & ABS2, ONE2);
    u64 dg = add2(g & ABS2, ONE2);
    u64 dd = mul2(df, dg);
    float dl, dh; unpk(dd, dl, dh);
    u64 rr = pk(rcpf(dl), rcpf(dh));
    return mul2(mul2(f, g), rr);
}

__global__ void start_kernel(const float* __restrict__ x,
                             const float* __restrict__ sw,
                             float* __restrict__ out) {
    int idx = blockIdx.x * blockDim.x + threadIdx.x;  // over B*T
    if (idx < BB * TT) {
        float xv = x[idx];
        #pragma unroll
        for (int o = 0; o < W; o++) g_h0[(size_t)idx * W + o] = sw[o] * xv;
        out[idx] = 0.f;
    }
}

// Row stride padded: R % 8 == 2 keeps the transpose store pattern spread.
__host__ __device__ __forceinline__ int padR(int d) {
    int R = TILE + 2 * d;
    R += ((2 - (R & 7)) + 8) & 7;
    return R;
}

// Dynamic smem layout (floats):
//  [0    :1536)  conv+gate weights, ((k*16+i)*32 + half*16 + o); half0=f, half1=g
//  [1536 :1792)  res weights transposed rsm[i][o]
//  [1792 :1808)  mixer msm[o]
//  [1808 :1824)  conv bias, [1824:1840) gate bias, [1840:1856) res bias
//  [1856 :    )  h tile, channel-major: hT[ch][R]
__global__ __launch_bounds__(NTH, 2)
void layer5_kernel(const float* __restrict__ cw, const float* __restrict__ cb,
                   const float* __restrict__ gw, const float* __restrict__ gb,
                   const float* __restrict__ rw, const float* __restrict__ rb,
                   const float* __restrict__ mix, float* __restrict__ out,
                   int li, int d, int last)
{
    extern __shared__ float sh[];
    const float* hin  = (li & 1) ? g_h1 : g_h0;
    float*       hout = (li & 1) ? g_h0 : g_h1;
    const int b   = blockIdx.y;
    const int t0  = blockIdx.x * TILE;
    const int tid = threadIdx.x;
    const int R   = padR(d);
    float* hT = sh + HOFF;

    // ---- weight prep (once per block) ----
    for (int w = tid; w < 1536; w += NTH) {
        int k = w >> 9, rem = w & 511;
        int i = rem >> 5, half = (rem >> 4) & 1, o = rem & 15;
        const float* src = half ? gw : cw;
        sh[w] = src[li * 768 + o * 48 + i * 3 + k];
    }
    for (int w = tid; w < 256; w += NTH) {
        int i = w >> 4, o = w & 15;
        sh[1536 + w] = last ? 0.f : rw[li * 256 + o * 16 + i];
    }
    if (tid < 16) {
        sh[1792 + tid] = mix[li * 16 + tid];
        sh[1808 + tid] = cb[li * 16 + tid];
        sh[1824 + tid] = gb[li * 16 + tid];
        sh[1840 + tid] = last ? 0.f : rb[li * 16 + tid];
    }

    // ---- h tile load, transposing [t][ch] -> [ch][t] ----
    {
        const int n4 = (TILE + 2 * d) * 4;  // float4 chunks
        for (int idx = tid; idx < n4; idx += NTH) {
            int r = idx >> 2, c = idx & 3;
            int gt = t0 - 2 * d + r;
            float4 v = make_float4(0.f, 0.f, 0.f, 0.f);
            if (gt >= 0)
                v = *(const float4*)(hin + ((size_t)b * TT + gt) * W + 4 * c);
            hT[(4 * c + 0) * R + r] = v.x;
            hT[(4 * c + 1) * R + r] = v.y;
            hT[(4 * c + 2) * R + r] = v.z;
            hT[(4 * c + 3) * R + r] = v.w;
        }
    }
    __syncthreads();

    // ---- conv: thread owns ts t0 + tid + 128*m, m = 0..3 ----
    u64 f[4][8], g[4][8];
    {
        const u64* bp = (const u64*)(sh + 1808);
        #pragma unroll
        for (int p = 0; p < 8; p++) {
            u64 cbv = bp[p], gbv = bp[8 + p];
            #pragma unroll
            for (int m = 0; m < 4; m++) { f[m][p] = cbv; g[m][p] = gbv; }
        }
    }

    #pragma unroll 1
    for (int k = 0; k < 3; k++) {
        const float* tp = hT + k * d + tid;
        #pragma unroll 4
        for (int i = 0; i < 16; i++) {
            const float* row = tp + i * R;
            u64 hp0 = pk2(row[0]);
            u64 hp1 = pk2(row[128]);
            u64 hp2 = pk2(row[256]);
            u64 hp3 = pk2(row[384]);
            const ulonglong2* wp = (const ulonglong2*)(sh) + (k * 16 + i) * 8;
            #pragma unroll
            for (int q = 0; q < 4; q++) {
                ulonglong2 wf = wp[q];
                ulonglong2 wg = wp[4 + q];
                f[0][2*q]   = fma2(wf.x, hp0, f[0][2*q]);
                f[0][2*q+1] = fma2(wf.y, hp0, f[0][2*q+1]);
                f[1][2*q]   = fma2(wf.x, hp1, f[1][2*q]);
                f[1][2*q+1] = fma2(wf.y, hp1, f[1][2*q+1]);
                f[2][2*q]   = fma2(wf.x, hp2, f[2][2*q]);
                f[2][2*q+1] = fma2(wf.y, hp2, f[2][2*q+1]);
                f[3][2*q]   = fma2(wf.x, hp3, f[3][2*q]);
                f[3][2*q+1] = fma2(wf.y, hp3, f[3][2*q+1]);
                g[0][2*q]   = fma2(wg.x, hp0, g[0][2*q]);
                g[0][2*q+1] = fma2(wg.y, hp0, g[0][2*q+1]);
                g[1][2*q]   = fma2(wg.x, hp1, g[1][2*q]);
                g[1][2*q+1] = fma2(wg.y, hp1, g[1][2*q+1]);
                g[2][2*q]   = fma2(wg.x, hp2, g[2][2*q]);
                g[2][2*q+1] = fma2(wg.y, hp2, g[2][2*q+1]);
                g[3][2*q]   = fma2(wg.x, hp3, g[3][2*q]);
                g[3][2*q+1] = fma2(wg.y, hp3, g[3][2*q+1]);
            }
        }
    }

    // ---- gated activation (z overwrites f; g dies here) ----
    #pragma unroll
    for (int m = 0; m < 4; m++)
        #pragma unroll
        for (int p = 0; p < 8; p++)
            f[m][p] = ssz(f[m][p], g[m][p]);

    // ---- mixer: per-ts dot(mix, z), scalar RMW into out (coalesced) ----
    {
        const u64* mp = (const u64*)(sh + 1792);
        #pragma unroll
        for (int m = 0; m < 4; m++) {
            u64 acc = mul2(mp[0], f[m][0]);
            #pragma unroll
            for (int p = 1; p < 8; p++) acc = fma2(mp[p], f[m][p], acc);
            float a, c; unpk(acc, a, c);
            out[(size_t)b * TT + t0 + tid + 128 * m] += a + c;
        }
    }

    // ---- residual + write next h; res weights loaded ONCE for all 4 ts ----
    if (!last) {
        const u64* rbp = (const u64*)(sh + 1840);
        u64 hn[4][8];
        #pragma unroll
        for (int m = 0; m < 4; m++) {
            const ulonglong2* s =
                (const ulonglong2*)(hin + ((size_t)b * TT + t0 + tid + 128 * m) * W);
            #pragma unroll
            for (int q = 0; q < 4; q++) {
                ulonglong2 a = s[q];
                hn[m][2*q]   = add2(a.x, rbp[2*q]);
                hn[m][2*q+1] = add2(a.y, rbp[2*q+1]);
            }
        }
        #pragma unroll 4
        for (int i = 0; i < 16; i++) {
            const ulonglong2* rp = (const ulonglong2*)(sh + 1536) + i * 4;
            ulonglong2 r0 = rp[0], r1 = rp[1], r2 = rp[2], r3 = rp[3];
            #pragma unroll
            for (int m = 0; m < 4; m++) {
                float lo, hi; unpk(f[m][i >> 1], lo, hi);
                u64 zp = pk2((i & 1) ? hi : lo);
                hn[m][0] = fma2(r0.x, zp, hn[m][0]);
                hn[m][1] = fma2(r0.y, zp, hn[m][1]);
                hn[m][2] = fma2(r1.x, zp, hn[m][2]);
                hn[m][3] = fma2(r1.y, zp, hn[m][3]);
                hn[m][4] = fma2(r2.x, zp, hn[m][4]);
                hn[m][5] = fma2(r2.y, zp, hn[m][5]);
                hn[m][6] = fma2(r3.x, zp, hn[m][6]);
                hn[m][7] = fma2(r3.y, zp, hn[m][7]);
            }
        }
        #pragma unroll
        for (int m = 0; m < 4; m++) {
            ulonglong2* o =
                (ulonglong2*)(hout + ((size_t)b * TT + t0 + tid + 128 * m) * W);
            #pragma unroll
            for (int q = 0; q < 4; q++)
                o[q] = make_ulonglong2(hn[m][2*q], hn[m][2*q+1]);
        }
    }
}

extern "C" void kernel_launch(void* const* d_in, const int* in_sizes, int n_in,
                              void* d_out, int out_size) {
    const float* x   = (const float*)d_in[0];
    const float* sw  = (const float*)d_in[1];
    const float* cw  = (const float*)d_in[2];
    const float* cb  = (const float*)d_in[3];
    const float* gw  = (const float*)d_in[4];
    const float* gb  = (const float*)d_in[5];
    const float* rw  = (const float*)d_in[6];
    const float* rb  = (const float*)d_in[7];
    const float* mix = (const float*)d_in[8];
    float* out = (float*)d_out;

    static const int dil[NL] = {1,2,4,8,16,32,64,128,256,
                                1,2,4,8,16,32,64,128,256};

    const int max_smem = (HOFF + W * padR(256)) * (int)sizeof(float);
    cudaFuncSetAttribute(layer5_kernel,
                         cudaFuncAttributeMaxDynamicSharedMemorySize, max_smem);

    start_kernel<<<(BB * TT + 255) / 256, 256>>>(x, sw, out);

    dim3 grid(TT / TILE, BB);
    for (int li = 0; li < NL; li++) {
        int d = dil[li];
        int smem = (HOFF + W * padR(d)) * (int)sizeof(float);
        layer5_kernel<<<grid, NTH, smem>>>(
            cw, cb, gw, gb, rw, rb, mix, out,
            li, d, (li == NL - 1) ? 1 : 0);
    }
}

// round 6
// speedup vs baseline: 1.5173x; 1.1588x over previous
#include <cuda_runtime.h>
#include <cuda_bf16.h>

#define TT   65536
#define BB   4
#define W    16
#define NL   18
#define TILE 576       // timesteps per CTA (= NTH*3)
#define NTH  192       // thread owns ts tid + 192*m, m=0..2
#define HOFF 1856      // float offset of h tile in dynamic smem

typedef unsigned long long u64;

__device__ float g_h0[(size_t)BB * TT * W];
__device__ float g_h1[(size_t)BB * TT * W];

__device__ __forceinline__ u64 pk2(float x){ u64 r; asm("mov.b64 %0,{%1,%1};":"=l"(r):"f"(x)); return r; }
__device__ __forceinline__ u64 pk(float lo, float hi){ u64 r; asm("mov.b64 %0,{%1,%2};":"=l"(r):"f"(lo),"f"(hi)); return r; }
__device__ __forceinline__ void unpk(u64 v, float& lo, float& hi){ asm("mov.b64 {%0,%1},%2;":"=f"(lo),"=f"(hi):"l"(v)); }
__device__ __forceinline__ u64 fma2(u64 a, u64 b, u64 c){ u64 d; asm("fma.rn.f32x2 %0,%1,%2,%3;":"=l"(d):"l"(a),"l"(b),"l"(c)); return d; }
__device__ __forceinline__ u64 mul2(u64 a, u64 b){ u64 d; asm("mul.rn.f32x2 %0,%1,%2;":"=l"(d):"l"(a),"l"(b)); return d; }
__device__ __forceinline__ u64 add2(u64 a, u64 b){ u64 d; asm("add.rn.f32x2 %0,%1,%2;":"=l"(d):"l"(a),"l"(b)); return d; }
__device__ __forceinline__ float rcpf(float x){ float r; asm("rcp.approx.f32 %0,%1;":"=f"(r):"f"(x)); return r; }

#define ABS2 0x7FFFFFFF7FFFFFFFull
#define ONE2 0x3F8000003F800000ull

// z = softsign(f)*softsign(g) = f*g / ((1+|f|)(1+|g|)), packed over 2 channels
__device__ __forceinline__ u64 ssz(u64 f, u64 g){
    u64 df = add2(f & ABS2, ONE2);
    u64 dg = add2(g & ABS2, ONE2);
    u64 dd = mul2(df, dg);
    float dl, dh; unpk(dd, dl, dh);
    u64 rr = pk(rcpf(dl), rcpf(dh));
    return mul2(mul2(f, g), rr);
}

__global__ void start_kernel(const float* __restrict__ x,
                             const float* __restrict__ sw,
                             float* __restrict__ out) {
    int idx = blockIdx.x * blockDim.x + threadIdx.x;  // over B*T
    if (idx < BB * TT) {
        float xv = x[idx];
        #pragma unroll
        for (int o = 0; o < W; o++) g_h0[(size_t)idx * W + o] = sw[o] * xv;
        out[idx] = 0.f;
    }
}

// Row stride padded: R % 8 == 2 keeps transpose-store/bank pattern spread.
__host__ __device__ __forceinline__ int padR(int d) {
    int R = TILE + 2 * d;
    R += ((2 - (R & 7)) + 8) & 7;
    return R;
}

// Dynamic smem layout (floats):
//  [0    :1536)  conv+gate weights, ((k*16+i)*32 + half*16 + o); half0=f, half1=g
//  [1536 :1792)  res weights transposed rsm[i][o]
//  [1792 :1808)  mixer msm[o]
//  [1808 :1824)  conv bias, [1824:1840) gate bias, [1840:1856) res bias
//  [1856 :    )  h tile, channel-major: hT[ch][R]
__global__ __launch_bounds__(NTH, 2)
void layer6_kernel(const float* __restrict__ cw, const float* __restrict__ cb,
                   const float* __restrict__ gw, const float* __restrict__ gb,
                   const float* __restrict__ rw, const float* __restrict__ rb,
                   const float* __restrict__ mix, float* __restrict__ out,
                   int li, int d, int last)
{
    extern __shared__ float sh[];
    const float* hin  = (li & 1) ? g_h1 : g_h0;
    float*       hout = (li & 1) ? g_h0 : g_h1;
    const int b   = blockIdx.y;
    const int t0  = blockIdx.x * TILE;
    const int tid = threadIdx.x;
    const int R   = padR(d);
    float* hT = sh + HOFF;

    // ---- weight prep (once per block) ----
    for (int w = tid; w < 1536; w += NTH) {
        int k = w >> 9, rem = w & 511;
        int i = rem >> 5, half = (rem >> 4) & 1, o = rem & 15;
        const float* src = half ? gw : cw;
        sh[w] = src[li * 768 + o * 48 + i * 3 + k];
    }
    for (int w = tid; w < 256; w += NTH) {
        int i = w >> 4, o = w & 15;
        sh[1536 + w] = last ? 0.f : rw[li * 256 + o * 16 + i];
    }
    if (tid < 16) {
        sh[1792 + tid] = mix[li * 16 + tid];
        sh[1808 + tid] = cb[li * 16 + tid];
        sh[1824 + tid] = gb[li * 16 + tid];
        sh[1840 + tid] = last ? 0.f : rb[li * 16 + tid];
    }

    // ---- h tile load, transposing [t][ch] -> [ch][t]; zero-fill OOB ----
    {
        const int n4 = (TILE + 2 * d) * 4;  // float4 chunks
        for (int idx = tid; idx < n4; idx += NTH) {
            int r = idx >> 2, c = idx & 3;
            int gt = t0 - 2 * d + r;
            float4 v = make_float4(0.f, 0.f, 0.f, 0.f);
            if (gt >= 0 && gt < TT)
                v = *(const float4*)(hin + ((size_t)b * TT + gt) * W + 4 * c);
            hT[(4 * c + 0) * R + r] = v.x;
            hT[(4 * c + 1) * R + r] = v.y;
            hT[(4 * c + 2) * R + r] = v.z;
            hT[(4 * c + 3) * R + r] = v.w;
        }
    }
    __syncthreads();

    // ---- conv: thread owns ts t0 + tid + 192*m, m = 0..2 ----
    const bool v0 = (t0 + tid)       < TT;
    const bool v1 = (t0 + tid + 192) < TT;
    const bool v2 = (t0 + tid + 384) < TT;

    u64 f[3][8], g[3][8];
    {
        const u64* bp = (const u64*)(sh + 1808);
        #pragma unroll
        for (int p = 0; p < 8; p++) {
            u64 cbv = bp[p], gbv = bp[8 + p];
            #pragma unroll
            for (int m = 0; m < 3; m++) { f[m][p] = cbv; g[m][p] = gbv; }
        }
    }

    #pragma unroll 1
    for (int k = 0; k < 3; k++) {
        const float* tp = hT + k * d + tid;
        #pragma unroll 4
        for (int i = 0; i < 16; i++) {
            const float* row = tp + i * R;
            u64 hp0 = pk2(row[0]);
            u64 hp1 = pk2(row[192]);
            u64 hp2 = pk2(row[384]);
            const ulonglong2* wp = (const ulonglong2*)(sh) + (k * 16 + i) * 8;
            #pragma unroll
            for (int q = 0; q < 4; q++) {
                ulonglong2 wf = wp[q];
                ulonglong2 wg = wp[4 + q];
                f[0][2*q]   = fma2(wf.x, hp0, f[0][2*q]);
                f[0][2*q+1] = fma2(wf.y, hp0, f[0][2*q+1]);
                f[1][2*q]   = fma2(wf.x, hp1, f[1][2*q]);
                f[1][2*q+1] = fma2(wf.y, hp1, f[1][2*q+1]);
                f[2][2*q]   = fma2(wf.x, hp2, f[2][2*q]);
                f[2][2*q+1] = fma2(wf.y, hp2, f[2][2*q+1]);
                g[0][2*q]   = fma2(wg.x, hp0, g[0][2*q]);
                g[0][2*q+1] = fma2(wg.y, hp0, g[0][2*q+1]);
                g[1][2*q]   = fma2(wg.x, hp1, g[1][2*q]);
                g[1][2*q+1] = fma2(wg.y, hp1, g[1][2*q+1]);
                g[2][2*q]   = fma2(wg.x, hp2, g[2][2*q]);
                g[2][2*q+1] = fma2(wg.y, hp2, g[2][2*q+1]);
            }
        }
    }

    // ---- gated activation (z overwrites f; g dies here) ----
    #pragma unroll
    for (int m = 0; m < 3; m++)
        #pragma unroll
        for (int p = 0; p < 8; p++)
            f[m][p] = ssz(f[m][p], g[m][p]);

    // ---- mixer: per-ts dot(mix, z), scalar RMW into out (coalesced) ----
    {
        const u64* mp = (const u64*)(sh + 1792);
        #pragma unroll
        for (int m = 0; m < 3; m++) {
            u64 acc = mul2(mp[0], f[m][0]);
            #pragma unroll
            for (int p = 1; p < 8; p++) acc = fma2(mp[p], f[m][p], acc);
            float a, c; unpk(acc, a, c);
            bool vm = (m == 0) ? v0 : (m == 1) ? v1 : v2;
            if (vm) out[(size_t)b * TT + t0 + tid + 192 * m] += a + c;
        }
    }

    // ---- residual + write next h; res weights loaded ONCE for all 3 ts ----
    if (!last) {
        const u64* rbp = (const u64*)(sh + 1840);
        u64 hn[3][8];
        #pragma unroll
        for (int m = 0; m < 3; m++) {
            bool vm = (m == 0) ? v0 : (m == 1) ? v1 : v2;
            if (vm) {
                const ulonglong2* s =
                    (const ulonglong2*)(hin + ((size_t)b * TT + t0 + tid + 192 * m) * W);
                #pragma unroll
                for (int q = 0; q < 4; q++) {
                    ulonglong2 a = s[q];
                    hn[m][2*q]   = add2(a.x, rbp[2*q]);
                    hn[m][2*q+1] = add2(a.y, rbp[2*q+1]);
                }
            } else {
                #pragma unroll
                for (int p = 0; p < 8; p++) hn[m][p] = 0ull;
            }
        }
        #pragma unroll 4
        for (int i = 0; i < 16; i++) {
            const ulonglong2* rp = (const ulonglong2*)(sh + 1536) + i * 4;
            ulonglong2 r0 = rp[0], r1 = rp[1], r2 = rp[2], r3 = rp[3];
            #pragma unroll
            for (int m = 0; m < 3; m++) {
                float lo, hi; unpk(f[m][i >> 1], lo, hi);
                u64 zp = pk2((i & 1) ? hi : lo);
                hn[m][0] = fma2(r0.x, zp, hn[m][0]);
                hn[m][1] = fma2(r0.y, zp, hn[m][1]);
                hn[m][2] = fma2(r1.x, zp, hn[m][2]);
                hn[m][3] = fma2(r1.y, zp, hn[m][3]);
                hn[m][4] = fma2(r2.x, zp, hn[m][4]);
                hn[m][5] = fma2(r2.y, zp, hn[m][5]);
                hn[m][6] = fma2(r3.x, zp, hn[m][6]);
                hn[m][7] = fma2(r3.y, zp, hn[m][7]);
            }
        }
        #pragma unroll
        for (int m = 0; m < 3; m++) {
            bool vm = (m == 0) ? v0 : (m == 1) ? v1 : v2;
            if (vm) {
                ulonglong2* o =
                    (ulonglong2*)(hout + ((size_t)b * TT + t0 + tid + 192 * m) * W);
                #pragma unroll
                for (int q = 0; q < 4; q++)
                    o[q] = make_ulonglong2(hn[m][2*q], hn[m][2*q+1]);
            }
        }
    }
}

extern "C" void kernel_launch(void* const* d_in, const int* in_sizes, int n_in,
                              void* d_out, int out_size) {
    const float* x   = (const float*)d_in[0];
    const float* sw  = (const float*)d_in[1];
    const float* cw  = (const float*)d_in[2];
    const float* cb  = (const float*)d_in[3];
    const float* gw  = (const float*)d_in[4];
    const float* gb  = (const float*)d_in[5];
    const float* rw  = (const float*)d_in[6];
    const float* rb  = (const float*)d_in[7];
    const float* mix = (const float*)d_in[8];
    float* out = (float*)d_out;

    static const int dil[NL] = {1,2,4,8,16,32,64,128,256,
                                1,2,4,8,16,32,64,128,256};

    const int max_smem = (HOFF + W * padR(256)) * (int)sizeof(float);
    cudaFuncSetAttribute(layer6_kernel,
                         cudaFuncAttributeMaxDynamicSharedMemorySize, max_smem);

    start_kernel<<<(BB * TT + 255) / 256, 256>>>(x, sw, out);

    const int nblk = (TT + TILE - 1) / TILE;   // 114, last block partial
    dim3 grid(nblk, BB);
    for (int li = 0; li < NL; li++) {
        int d = dil[li];
        int smem = (HOFF + W * padR(d)) * (int)sizeof(float);
        layer6_kernel<<<grid, NTH, smem>>>(
            cw, cb, gw, gb, rw, rb, mix, out,
            li, d, (li == NL - 1) ? 1 : 0);
    }
}